// round 10
// baseline (speedup 1.0000x reference)
#include <cuda_runtime.h>
#include <cuda_fp16.h>

#define NN 200000
#define NNZC 3200000
#define NG 256
#define SCAN_BS 1024
#define NBLK_SCAN ((NN + SCAN_BS - 1) / SCAN_BS)   // 196

// ---- packed fp32x2 helpers (sm_103a FFMA2 path) ----
#define PACK2(dst, lo, hi) \
    asm("mov.b64 %0, {%1, %2};" : "=l"(dst) : "r"(__float_as_uint(lo)), "r"(__float_as_uint(hi)))
#define FFMA2(acc, a, b) \
    asm("fma.rn.f32x2 %0, %1, %2, %0;" : "+l"(acc) : "l"(a), "l"(b))
__device__ __forceinline__ float hsum2(unsigned long long v) {
    unsigned int u, w;
    asm("mov.b64 {%0, %1}, %2;" : "=r"(u), "=r"(w) : "l"(v));
    return __uint_as_float(u) + __uint_as_float(w);
}

// ---------------- device scratch (no allocations allowed) ----------------
__device__ __align__(16) int    g_ptr_up[NN + 1];
__device__ __align__(16) int    g_ptr_dn[NN + 1];
__device__ __align__(16) int    g_cnt_up[NN];       // counts, then cursor
__device__ __align__(16) int    g_cnt_dn[NN];
__device__ __align__(16) int2   g_eu[NNZC];         // packed (col, val bits)
__device__ __align__(16) int2   g_ed[NNZC];
__device__ __align__(16) int    g_bsum[2][NBLK_SCAN];
__device__ __align__(16) __half g_H16[(size_t)NN * 32];   // per-layer GEMM output (fp16)
__device__ __align__(16) __half g_Xa16[(size_t)NN * 32];  // layer-1 agg output (fp16)
__device__ __align__(16) __half g_Xb16[(size_t)NN * 32];  // layer-2 agg output (fp16)
__device__ __align__(16) __half g_U16[(size_t)NN * 64];   // layer-4 aggregated up|dn (fp16)
__device__ __align__(16) float  g_S2a[NN];          // exp(s2) head0 / up
__device__ __align__(16) float  g_S2b[NN];          // exp(s2) head1 / down
__device__ __align__(16) float  g_psum[NG * 64];
__device__ __align__(16) float  g_pcnt[NG];

// ---------------- zero scratch ----------------
__global__ void zero_kernel() {
    int i = blockIdx.x * blockDim.x + threadIdx.x;
    if (i < NN) { g_cnt_up[i] = 0; g_cnt_dn[i] = 0; }
    if (i < NG * 64) g_psum[i] = 0.f;
    if (i < NG) g_pcnt[i] = 0.f;
}

// ---------------- CSR build (up + down fused) ----------------
// 4 edges per thread via int4 loads; atomics are fire-and-forget (RED).
__global__ void count_kernel(const int* __restrict__ ru, const int* __restrict__ rd) {
    int e4 = blockIdx.x * blockDim.x + threadIdx.x;
    if (e4 >= NNZC / 4) return;
    int4 r = ((const int4*)ru)[e4];
    atomicAdd(&g_cnt_up[r.x], 1); atomicAdd(&g_cnt_up[r.y], 1);
    atomicAdd(&g_cnt_up[r.z], 1); atomicAdd(&g_cnt_up[r.w], 1);
    int4 s = ((const int4*)rd)[e4];
    atomicAdd(&g_cnt_dn[s.x], 1); atomicAdd(&g_cnt_dn[s.y], 1);
    atomicAdd(&g_cnt_dn[s.z], 1); atomicAdd(&g_cnt_dn[s.w], 1);
}

__global__ __launch_bounds__(SCAN_BS) void scan1_kernel() {
    __shared__ int s[SCAN_BS];
    int which = blockIdx.y;
    const int* cnt = which ? g_cnt_dn : g_cnt_up;
    int* ptr = which ? g_ptr_dn : g_ptr_up;
    int tid = threadIdx.x;
    int idx = blockIdx.x * SCAN_BS + tid;
    int c = (idx < NN) ? cnt[idx] : 0;
    s[tid] = c;
    __syncthreads();
    for (int off = 1; off < SCAN_BS; off <<= 1) {
        int v = (tid >= off) ? s[tid - off] : 0;
        __syncthreads();
        s[tid] += v;
        __syncthreads();
    }
    if (idx < NN) ptr[idx] = s[tid] - c;
    if (tid == SCAN_BS - 1) g_bsum[which][blockIdx.x] = s[tid];
}

// folds the block-sum prefix in: each block reduces the block sums below its scan1 block.
__global__ void scan3_kernel() {
    __shared__ int s[256];
    int which = blockIdx.y;
    int* ptr = which ? g_ptr_dn : g_ptr_up;
    int* cur = which ? g_cnt_dn : g_cnt_up;
    int tid = threadIdx.x;
    int g = (blockIdx.x * 256) / SCAN_BS;
    int contrib = (tid < g) ? g_bsum[which][tid] : 0;   // g <= 195 < 256
    s[tid] = contrib;
    __syncthreads();
    for (int off = 128; off; off >>= 1) {
        if (tid < off) s[tid] += s[tid + off];
        __syncthreads();
    }
    int prefix = s[0];
    int i = blockIdx.x * 256 + tid;
    if (i < NN) {
        int p = ptr[i] + prefix;
        ptr[i] = p;
        cur[i] = p;
    }
    if (i == 0) ptr[NN] = NNZC;
}

// 2 edges per thread -> 4 independent atomic/scatter chains for latency hiding.
__global__ void fill_kernel(const int* __restrict__ ru, const float* __restrict__ vu,
                            const int* __restrict__ rd, const float* __restrict__ vd) {
    int e2 = blockIdx.x * blockDim.x + threadIdx.x;
    if (e2 >= NNZC / 2) return;
    int e = e2 * 2;
    int2 r0 = ((const int2*)ru)[e2];
    int2 c0 = ((const int2*)(ru + NNZC))[e2];
    float2 v0 = ((const float2*)vu)[e2];
    int2 r1 = ((const int2*)rd)[e2];
    int2 c1 = ((const int2*)(rd + NNZC))[e2];
    float2 v1 = ((const float2*)vd)[e2];
    (void)e;
    int pa = atomicAdd(&g_cnt_up[r0.x], 1);
    int pb = atomicAdd(&g_cnt_up[r0.y], 1);
    int pc = atomicAdd(&g_cnt_dn[r1.x], 1);
    int pd = atomicAdd(&g_cnt_dn[r1.y], 1);
    g_eu[pa] = make_int2(c0.x, __float_as_int(v0.x));
    g_eu[pb] = make_int2(c0.y, __float_as_int(v0.y));
    g_ed[pc] = make_int2(c1.x, __float_as_int(v1.x));
    g_ed[pd] = make_int2(c1.y, __float_as_int(v1.y));
}

// ---------------- layers 1/2 GEMM (f32x2) + fused T = exp(|h| @ a2) ----------------
// Two heads of width 16 concatenated (FO=32), W layout [2][FI][16], a2 [2][16].
// srcHalf=1: stage X from g_Xa16 (half2). Writes fp16 H and T into S2a/S2b.
template <int FI, int NT, int SRCHALF>
__global__ __launch_bounds__(256) void gemm12_kernel(const float* __restrict__ Xext,
                                                     const float* __restrict__ W,
                                                     const float* __restrict__ a2) {
    constexpr int FO = 32;
    constexpr int G = 256 / FO;                 // 8
    constexpr int TN = NT / G;
    __shared__ unsigned long long Wsd[(FI / 2) * FO];   // paired (w_k, w_{k+1}) per output j
    __shared__ __align__(16) float Xs[NT * FI];
    __shared__ float a2s[FO];

    int tid = threadIdx.x;
    for (int i = tid; i < (FI / 2) * FO; i += 256) {
        int k2 = i / FO, j = i % FO;
        float wlo, whi;
        if (j < 16) {
            wlo = W[(2 * k2) * 16 + j];
            whi = W[(2 * k2 + 1) * 16 + j];
        } else {
            wlo = W[FI * 16 + (2 * k2) * 16 + (j - 16)];
            whi = W[FI * 16 + (2 * k2 + 1) * 16 + (j - 16)];
        }
        unsigned long long dd; PACK2(dd, wlo, whi);
        Wsd[i] = dd;
    }
    if (tid < FO) a2s[tid] = a2[tid];
    int nb = blockIdx.x * NT;
    if (SRCHALF) {
        const __half2* src = (const __half2*)g_Xa16 + (size_t)nb * (FI / 2);
        float2* dst = (float2*)Xs;
        for (int i = tid; i < NT * FI / 2; i += 256) dst[i] = __half22float2(src[i]);
    } else {
        const float4* src = (const float4*)(Xext + (size_t)nb * FI);
        float4* dst = (float4*)Xs;
        for (int i = tid; i < NT * FI / 4; i += 256) dst[i] = src[i];
    }
    __syncthreads();

    int j = tid % FO, grp = tid / FO, lane = tid & 31;
    unsigned long long acc[TN];
#pragma unroll
    for (int t = 0; t < TN; ++t) acc[t] = 0ull;
    const float4* Xs4 = (const float4*)Xs;
#pragma unroll 4
    for (int k4 = 0; k4 < FI / 4; ++k4) {
        unsigned long long w01 = Wsd[(2 * k4 + 0) * FO + j];
        unsigned long long w23 = Wsd[(2 * k4 + 1) * FO + j];
#pragma unroll
        for (int t = 0; t < TN; ++t) {
            float4 x = Xs4[(grp + G * t) * (FI / 4) + k4];
            unsigned long long x01, x23;
            PACK2(x01, x.x, x.y);
            PACK2(x23, x.z, x.w);
            FFMA2(acc[t], x01, w01);
            FFMA2(acc[t], x23, w23);
        }
    }
    float h[TN];
#pragma unroll
    for (int t = 0; t < TN; ++t) {
        h[t] = hsum2(acc[t]);
        int node = nb + grp + G * t;
        g_H16[(size_t)node * 32 + j] = __float2half_rn(h[t]);
    }
    float a = a2s[j];
#pragma unroll
    for (int t = 0; t < TN; ++t) {
        float v = fabsf(h[t]) * a;
        v += __shfl_xor_sync(0xffffffffu, v, 8);
        v += __shfl_xor_sync(0xffffffffu, v, 4);
        v += __shfl_xor_sync(0xffffffffu, v, 2);
        v += __shfl_xor_sync(0xffffffffu, v, 1);
        int node = nb + grp + G * t;
        if (lane == 0)  g_S2a[node] = __expf(v);   // head 0 (j 0..15)
        if (lane == 16) g_S2b[node] = __expf(v);   // head 1 (j 16..31)
    }
}

// ---------------- fused up+down agg, layers 1/2 (16 features/head) ----------------
// 4 sub-groups of 8 lanes; 2x unrolled dual accumulator chains for MLP.
__global__ __launch_bounds__(256) void agg16c_kernel(int sel) {
    int gw = (blockIdx.x * blockDim.x + threadIdx.x) >> 5;
    int lane = threadIdx.x & 31;
    int sub = lane >> 3, f2 = lane & 7;
    const __half2* __restrict__ H2 = (const __half2*)g_H16;  // row = 16 half2

    float2 r0, r1;
    {   // head 0: up graph, half2 cols [0,8)
        int start = g_ptr_up[gw], end = g_ptr_up[gw + 1];
        float d0 = 0.f, d1 = 0.f;
        float2 A0 = make_float2(0.f, 0.f), A1 = make_float2(0.f, 0.f);
        int e = start + sub;
        for (; e + 4 < end; e += 8) {
            int2 ca = g_eu[e];
            int2 cb = g_eu[e + 4];
            float ta = g_S2a[ca.x];
            float tb = g_S2a[cb.x];
            float2 ha = __half22float2(H2[(size_t)ca.x * 16 + f2]);
            float2 hb = __half22float2(H2[(size_t)cb.x * 16 + f2]);
            float wa = ta * __int_as_float(ca.y);
            float wb = tb * __int_as_float(cb.y);
            d0 += ta; A0.x += wa * ha.x; A0.y += wa * ha.y;
            d1 += tb; A1.x += wb * hb.x; A1.y += wb * hb.y;
        }
        if (e < end) {
            int2 ca = g_eu[e];
            float ta = g_S2a[ca.x];
            float2 ha = __half22float2(H2[(size_t)ca.x * 16 + f2]);
            float wa = ta * __int_as_float(ca.y);
            d0 += ta; A0.x += wa * ha.x; A0.y += wa * ha.y;
        }
        float d = d0 + d1;
        float2 acc = make_float2(A0.x + A1.x, A0.y + A1.y);
        acc.x += __shfl_xor_sync(0xffffffffu, acc.x, 8);
        acc.y += __shfl_xor_sync(0xffffffffu, acc.y, 8);
        d     += __shfl_xor_sync(0xffffffffu, d, 8);
        acc.x += __shfl_xor_sync(0xffffffffu, acc.x, 16);
        acc.y += __shfl_xor_sync(0xffffffffu, acc.y, 16);
        d     += __shfl_xor_sync(0xffffffffu, d, 16);
        float rd = (d > 0.f) ? 1.f / d : 0.f;
        r0 = make_float2(fmaxf(acc.x * rd, 0.f), fmaxf(acc.y * rd, 0.f));
    }
    {   // head 1: down graph, half2 cols [8,16)
        int start = g_ptr_dn[gw], end = g_ptr_dn[gw + 1];
        float d0 = 0.f, d1 = 0.f;
        float2 A0 = make_float2(0.f, 0.f), A1 = make_float2(0.f, 0.f);
        int e = start + sub;
        for (; e + 4 < end; e += 8) {
            int2 ca = g_ed[e];
            int2 cb = g_ed[e + 4];
            float ta = g_S2b[ca.x];
            float tb = g_S2b[cb.x];
            float2 ha = __half22float2(H2[(size_t)ca.x * 16 + 8 + f2]);
            float2 hb = __half22float2(H2[(size_t)cb.x * 16 + 8 + f2]);
            float wa = ta * __int_as_float(ca.y);
            float wb = tb * __int_as_float(cb.y);
            d0 += ta; A0.x += wa * ha.x; A0.y += wa * ha.y;
            d1 += tb; A1.x += wb * hb.x; A1.y += wb * hb.y;
        }
        if (e < end) {
            int2 ca = g_ed[e];
            float ta = g_S2b[ca.x];
            float2 ha = __half22float2(H2[(size_t)ca.x * 16 + 8 + f2]);
            float wa = ta * __int_as_float(ca.y);
            d0 += ta; A0.x += wa * ha.x; A0.y += wa * ha.y;
        }
        float d = d0 + d1;
        float2 acc = make_float2(A0.x + A1.x, A0.y + A1.y);
        acc.x += __shfl_xor_sync(0xffffffffu, acc.x, 8);
        acc.y += __shfl_xor_sync(0xffffffffu, acc.y, 8);
        d     += __shfl_xor_sync(0xffffffffu, d, 8);
        acc.x += __shfl_xor_sync(0xffffffffu, acc.x, 16);
        acc.y += __shfl_xor_sync(0xffffffffu, acc.y, 16);
        d     += __shfl_xor_sync(0xffffffffu, d, 16);
        float rd = (d > 0.f) ? 1.f / d : 0.f;
        r1 = make_float2(fmaxf(acc.x * rd, 0.f), fmaxf(acc.y * rd, 0.f));
    }
    if (lane < 8) {
        __half2* X2 = sel ? (__half2*)g_Xb16 : (__half2*)g_Xa16;
        X2[gw * 16 + f2]     = __float22half2_rn(r0);
        X2[gw * 16 + 8 + f2] = __float22half2_rn(r1);
    }
}

// ---------------- layer-4 T kernel (f32x2): both heads in one launch ----------------
__global__ __launch_bounds__(256) void t4_kernel(const float* __restrict__ W4,
                                                 const float* __restrict__ a24) {
    constexpr int FI = 32, FO = 64;
    constexpr int NT = 64;
    constexpr int G = 256 / FO;   // 4
    constexpr int TN = NT / G;    // 16
    __shared__ unsigned long long Wsd[(FI / 2) * FO];
    __shared__ __align__(16) float Xs[NT * FI];
    __shared__ float a2s[FO];
    __shared__ float sred[8 * TN];

    int headsel = blockIdx.y;
    const float* W = W4 + headsel * FI * FO;
    const float* a2 = a24 + headsel * FO;

    int tid = threadIdx.x;
    for (int i = tid; i < (FI / 2) * FO; i += 256) {
        int k2 = i / FO, j = i % FO;
        unsigned long long dd;
        PACK2(dd, W[(2 * k2) * FO + j], W[(2 * k2 + 1) * FO + j]);
        Wsd[i] = dd;
    }
    if (tid < FO) a2s[tid] = a2[tid];
    int nb = blockIdx.x * NT;
    {
        const __half2* src = (const __half2*)g_Xb16 + (size_t)nb * 16;
        float2* dst = (float2*)Xs;
        for (int i = tid; i < NT * 16; i += 256) dst[i] = __half22float2(src[i]);
    }
    __syncthreads();

    int j = tid % FO, grp = tid / FO, lane = tid & 31;
    unsigned long long acc[TN];
#pragma unroll
    for (int t = 0; t < TN; ++t) acc[t] = 0ull;
    const float4* Xs4 = (const float4*)Xs;
#pragma unroll
    for (int k4 = 0; k4 < FI / 4; ++k4) {
        unsigned long long w01 = Wsd[(2 * k4 + 0) * FO + j];
        unsigned long long w23 = Wsd[(2 * k4 + 1) * FO + j];
#pragma unroll
        for (int t = 0; t < TN; ++t) {
            float4 x = Xs4[(grp + G * t) * (FI / 4) + k4];
            unsigned long long x01, x23;
            PACK2(x01, x.x, x.y);
            PACK2(x23, x.z, x.w);
            FFMA2(acc[t], x01, w01);
            FFMA2(acc[t], x23, w23);
        }
    }
    float a = a2s[j];
    int wib = tid >> 5;
#pragma unroll
    for (int t = 0; t < TN; ++t) {
        float v = fabsf(hsum2(acc[t])) * a;
        for (int off = 16; off; off >>= 1) v += __shfl_xor_sync(0xffffffffu, v, off);
        if (lane == 0) sred[wib * TN + t] = v;
    }
    __syncthreads();
    if (j == 0) {
        float* Tout = headsel ? g_S2b : g_S2a;
#pragma unroll
        for (int t = 0; t < TN; ++t) {
            int node = nb + grp + G * t;
            Tout[node] = __expf(sred[(2 * grp) * TN + t] + sred[(2 * grp + 1) * TN + t]);
        }
    }
}

// ---------------- layer-4 aggregation of Xb16 (32 features, up|dn -> U16[64]) ----------------
// 2 sub-groups of 16 lanes; 2x unrolled dual chains.
__global__ __launch_bounds__(256) void agg4_kernel() {
    int gw = (blockIdx.x * blockDim.x + threadIdx.x) >> 5;
    int lane = threadIdx.x & 31;
    int sub = lane >> 4, f2 = lane & 15;
    const __half2* __restrict__ X2 = (const __half2*)g_Xb16;  // row = 16 half2

    float2 up, dn;
    {   // up graph
        int start = g_ptr_up[gw], end = g_ptr_up[gw + 1];
        float d0 = 0.f, d1 = 0.f;
        float2 A0 = make_float2(0.f, 0.f), A1 = make_float2(0.f, 0.f);
        int e = start + sub;
        for (; e + 2 < end; e += 4) {
            int2 ca = g_eu[e];
            int2 cb = g_eu[e + 2];
            float ta = g_S2a[ca.x];
            float tb = g_S2a[cb.x];
            float2 ha = __half22float2(X2[(size_t)ca.x * 16 + f2]);
            float2 hb = __half22float2(X2[(size_t)cb.x * 16 + f2]);
            float wa = ta * __int_as_float(ca.y);
            float wb = tb * __int_as_float(cb.y);
            d0 += ta; A0.x += wa * ha.x; A0.y += wa * ha.y;
            d1 += tb; A1.x += wb * hb.x; A1.y += wb * hb.y;
        }
        if (e < end) {
            int2 ca = g_eu[e];
            float ta = g_S2a[ca.x];
            float2 ha = __half22float2(X2[(size_t)ca.x * 16 + f2]);
            float wa = ta * __int_as_float(ca.y);
            d0 += ta; A0.x += wa * ha.x; A0.y += wa * ha.y;
        }
        float d = d0 + d1;
        float2 acc = make_float2(A0.x + A1.x, A0.y + A1.y);
        acc.x += __shfl_xor_sync(0xffffffffu, acc.x, 16);
        acc.y += __shfl_xor_sync(0xffffffffu, acc.y, 16);
        d     += __shfl_xor_sync(0xffffffffu, d, 16);
        float rd = (d > 0.f) ? 1.f / d : 0.f;
        up = make_float2(acc.x * rd, acc.y * rd);
    }
    {   // down graph
        int start = g_ptr_dn[gw], end = g_ptr_dn[gw + 1];
        float d0 = 0.f, d1 = 0.f;
        float2 A0 = make_float2(0.f, 0.f), A1 = make_float2(0.f, 0.f);
        int e = start + sub;
        for (; e + 2 < end; e += 4) {
            int2 ca = g_ed[e];
            int2 cb = g_ed[e + 2];
            float ta = g_S2b[ca.x];
            float tb = g_S2b[cb.x];
            float2 ha = __half22float2(X2[(size_t)ca.x * 16 + f2]);
            float2 hb = __half22float2(X2[(size_t)cb.x * 16 + f2]);
            float wa = ta * __int_as_float(ca.y);
            float wb = tb * __int_as_float(cb.y);
            d0 += ta; A0.x += wa * ha.x; A0.y += wa * ha.y;
            d1 += tb; A1.x += wb * hb.x; A1.y += wb * hb.y;
        }
        if (e < end) {
            int2 ca = g_ed[e];
            float ta = g_S2b[ca.x];
            float2 ha = __half22float2(X2[(size_t)ca.x * 16 + f2]);
            float wa = ta * __int_as_float(ca.y);
            d0 += ta; A0.x += wa * ha.x; A0.y += wa * ha.y;
        }
        float d = d0 + d1;
        float2 acc = make_float2(A0.x + A1.x, A0.y + A1.y);
        acc.x += __shfl_xor_sync(0xffffffffu, acc.x, 16);
        acc.y += __shfl_xor_sync(0xffffffffu, acc.y, 16);
        d     += __shfl_xor_sync(0xffffffffu, d, 16);
        float rd = (d > 0.f) ? 1.f / d : 0.f;
        dn = make_float2(acc.x * rd, acc.y * rd);
    }
    if (lane < 16) {
        __half2* U2 = (__half2*)g_U16;     // row = 32 half2: [0,16) up, [16,32) dn
        U2[gw * 32 + f2]      = __float22half2_rn(up);
        U2[gw * 32 + 16 + f2] = __float22half2_rn(dn);
    }
}

// ---------------- final GEMM (f32x2): out = relu(U16 @ W4flat) fused mean-pool ----------------
__global__ __launch_bounds__(256) void gemmfinal_kernel(const float* __restrict__ W4,
                                                        const int* __restrict__ batch) {
    constexpr int FI = 64, FO = 64;
    constexpr int NT = 64;
    constexpr int G = 4, TN = 16;
    __shared__ unsigned long long Wsd[(FI / 2) * FO];   // W4 flat [2][32][64] == [64][64]
    __shared__ __align__(16) float Xs[NT * FI];
    __shared__ float sred2[4][64];

    int tid = threadIdx.x;
    for (int i = tid; i < (FI / 2) * FO; i += 256) {
        int k2 = i / FO, j = i % FO;
        unsigned long long dd;
        PACK2(dd, W4[(2 * k2) * FO + j], W4[(2 * k2 + 1) * FO + j]);
        Wsd[i] = dd;
    }
    int nb = blockIdx.x * NT;
    {
        const __half2* src = (const __half2*)g_U16 + (size_t)nb * 32;
        float2* dst = (float2*)Xs;
        for (int i = tid; i < NT * 32; i += 256) dst[i] = __half22float2(src[i]);
    }
    __syncthreads();

    int j = tid % FO, grp = tid / FO;
    unsigned long long acc[TN];
#pragma unroll
    for (int t = 0; t < TN; ++t) acc[t] = 0ull;
    const float4* Xs4 = (const float4*)Xs;
#pragma unroll 4
    for (int k4 = 0; k4 < FI / 4; ++k4) {
        unsigned long long w01 = Wsd[(2 * k4 + 0) * FO + j];
        unsigned long long w23 = Wsd[(2 * k4 + 1) * FO + j];
#pragma unroll
        for (int t = 0; t < TN; ++t) {
            float4 x = Xs4[(grp + G * t) * (FI / 4) + k4];
            unsigned long long x01, x23;
            PACK2(x01, x.x, x.y);
            PACK2(x23, x.z, x.w);
            FFMA2(acc[t], x01, w01);
            FFMA2(acc[t], x23, w23);
        }
    }

    // pooled accumulation (batch sorted -> uniform iff first == last)
    int b0 = batch[nb];
    int bL = batch[nb + NT - 1];
    if (b0 == bL) {
        float s = 0.f;
#pragma unroll
        for (int t = 0; t < TN; ++t) s += fmaxf(hsum2(acc[t]), 0.f);
        sred2[grp][j] = s;
        __syncthreads();
        if (tid < 64) {
            float tot = sred2[0][tid] + sred2[1][tid] + sred2[2][tid] + sred2[3][tid];
            atomicAdd(&g_psum[b0 * 64 + tid], tot);
        }
        if (tid == 0) atomicAdd(&g_pcnt[b0], (float)NT);
    } else {
#pragma unroll
        for (int t = 0; t < TN; ++t) {
            int node = nb + grp + G * t;
            int b = batch[node];
            atomicAdd(&g_psum[b * 64 + j], fmaxf(hsum2(acc[t]), 0.f));
            if (j == 0) atomicAdd(&g_pcnt[b], 1.f);
        }
    }
}

__global__ void pool_softmax_kernel(float* __restrict__ out) {
    int g = blockIdx.x, j = threadIdx.x;
    __shared__ float rm[2], rs[2];
    float c = g_pcnt[g];
    float mean = g_psum[g * 64 + j] / fmaxf(c, 1.0f);
    float m = mean;
    for (int off = 16; off; off >>= 1) m = fmaxf(m, __shfl_xor_sync(0xffffffffu, m, off));
    if ((j & 31) == 0) rm[j >> 5] = m;
    __syncthreads();
    m = fmaxf(rm[0], rm[1]);
    float e = expf(mean - m);
    float s = e;
    for (int off = 16; off; off >>= 1) s += __shfl_xor_sync(0xffffffffu, s, off);
    if ((j & 31) == 0) rs[j >> 5] = s;
    __syncthreads();
    s = rs[0] + rs[1];
    out[g * 64 + j] = e / s;
}

// ---------------- launch ----------------
extern "C" void kernel_launch(void* const* d_in, const int* in_sizes, int n_in,
                              void* d_out, int out_size) {
    const float* X1   = (const float*)d_in[0];
    const int*   idxu = (const int*)d_in[1];
    const float* valu = (const float*)d_in[2];
    const int*   idxd = (const int*)d_in[3];
    const float* vald = (const float*)d_in[4];
    const int*   batch = (const int*)d_in[5];
    const float* W1  = (const float*)d_in[6];
    const float* a21 = (const float*)d_in[8];
    const float* W2  = (const float*)d_in[9];
    const float* a22 = (const float*)d_in[11];
    const float* W4  = (const float*)d_in[12];
    const float* a24 = (const float*)d_in[14];
    float* out = (float*)d_out;

    const int NB = (NN + 255) / 256;     // 782

    zero_kernel<<<NB, 256>>>();
    count_kernel<<<NNZC / 4 / 256, 256>>>(idxu, idxd);
    scan1_kernel<<<dim3(NBLK_SCAN, 2), SCAN_BS>>>();
    scan3_kernel<<<dim3(NB, 2), 256>>>();
    fill_kernel<<<NNZC / 2 / 256, 256>>>(idxu, valu, idxd, vald);

    // layer 1
    gemm12_kernel<128, 32, 0><<<NN / 32, 256>>>(X1, W1, a21);
    agg16c_kernel<<<NN / 8, 256>>>(0);          // -> g_Xa16
    // layer 2
    gemm12_kernel<32, 64, 1><<<NN / 64, 256>>>(nullptr, W2, a22);
    agg16c_kernel<<<NN / 8, 256>>>(1);          // -> g_Xb16
    // layer 4: both heads' T in one launch, aggregate Xb16, then GEMM+ReLU+pool
    t4_kernel<<<dim3(NN / 64, 2), 256>>>(W4, a24);
    agg4_kernel<<<NN / 8, 256>>>();
    gemmfinal_kernel<<<NN / 64, 256>>>(W4, batch);

    pool_softmax_kernel<<<NG, 64>>>(out);
}

// round 11
// speedup vs baseline: 1.1061x; 1.1061x over previous
#include <cuda_runtime.h>
#include <cuda_fp16.h>

#define NN 200000
#define NNZC 3200000
#define NG 256
#define SCAN_BS 1024
#define NBLK_SCAN ((NN + SCAN_BS - 1) / SCAN_BS)   // 196

// ---- packed fp32x2 helpers (sm_103a FFMA2 path) ----
#define PACK2(dst, lo, hi) \
    asm("mov.b64 %0, {%1, %2};" : "=l"(dst) : "r"(__float_as_uint(lo)), "r"(__float_as_uint(hi)))
#define FFMA2(acc, a, b) \
    asm("fma.rn.f32x2 %0, %1, %2, %0;" : "+l"(acc) : "l"(a), "l"(b))
__device__ __forceinline__ float hsum2(unsigned long long v) {
    unsigned int u, w;
    asm("mov.b64 {%0, %1}, %2;" : "=r"(u), "=r"(w) : "l"(v));
    return __uint_as_float(u) + __uint_as_float(w);
}

// ---------------- device scratch (no allocations allowed) ----------------
__device__ __align__(16) int    g_ptr_up[NN + 1];
__device__ __align__(16) int    g_ptr_dn[NN + 1];
__device__ __align__(16) int    g_cnt_up[NN];       // counts, then cursor
__device__ __align__(16) int    g_cnt_dn[NN];
__device__ __align__(16) int2   g_eu[NNZC];         // packed (col, val bits)
__device__ __align__(16) int2   g_ed[NNZC];
__device__ __align__(16) int    g_bsum[2][NBLK_SCAN];
__device__ __align__(16) __half g_H16[(size_t)NN * 32];   // per-layer GEMM output (fp16)
__device__ __align__(16) __half g_Xa16[(size_t)NN * 32];  // layer-1 agg output (fp16)
__device__ __align__(16) __half g_Xb16[(size_t)NN * 32];  // layer-2 agg output (fp16)
__device__ __align__(16) __half g_U16[(size_t)NN * 64];   // layer-4 aggregated up|dn (fp16)
__device__ __align__(16) float  g_S2a[NN];          // exp(s2) head0 / up
__device__ __align__(16) float  g_S2b[NN];          // exp(s2) head1 / down
__device__ __align__(16) float  g_psum[NG * 64];
__device__ __align__(16) float  g_pcnt[NG];

// ---------------- zero scratch ----------------
__global__ void zero_kernel() {
    int i = blockIdx.x * blockDim.x + threadIdx.x;
    if (i < NN) { g_cnt_up[i] = 0; g_cnt_dn[i] = 0; }
    if (i < NG * 64) g_psum[i] = 0.f;
    if (i < NG) g_pcnt[i] = 0.f;
}

// ---------------- CSR build (up + down fused) ----------------
// 4 edges per thread via int4 loads; atomics are fire-and-forget.
__global__ void count_kernel(const int* __restrict__ ru, const int* __restrict__ rd) {
    int e4 = blockIdx.x * blockDim.x + threadIdx.x;
    if (e4 >= NNZC / 4) return;
    int4 r = ((const int4*)ru)[e4];
    atomicAdd(&g_cnt_up[r.x], 1); atomicAdd(&g_cnt_up[r.y], 1);
    atomicAdd(&g_cnt_up[r.z], 1); atomicAdd(&g_cnt_up[r.w], 1);
    int4 s = ((const int4*)rd)[e4];
    atomicAdd(&g_cnt_dn[s.x], 1); atomicAdd(&g_cnt_dn[s.y], 1);
    atomicAdd(&g_cnt_dn[s.z], 1); atomicAdd(&g_cnt_dn[s.w], 1);
}

__global__ __launch_bounds__(SCAN_BS) void scan1_kernel() {
    __shared__ int s[SCAN_BS];
    int which = blockIdx.y;
    const int* cnt = which ? g_cnt_dn : g_cnt_up;
    int* ptr = which ? g_ptr_dn : g_ptr_up;
    int tid = threadIdx.x;
    int idx = blockIdx.x * SCAN_BS + tid;
    int c = (idx < NN) ? cnt[idx] : 0;
    s[tid] = c;
    __syncthreads();
    for (int off = 1; off < SCAN_BS; off <<= 1) {
        int v = (tid >= off) ? s[tid - off] : 0;
        __syncthreads();
        s[tid] += v;
        __syncthreads();
    }
    if (idx < NN) ptr[idx] = s[tid] - c;
    if (tid == SCAN_BS - 1) g_bsum[which][blockIdx.x] = s[tid];
}

// folds the block-sum prefix in: each block reduces the block sums below its scan1 block.
__global__ void scan3_kernel() {
    __shared__ int s[256];
    int which = blockIdx.y;
    int* ptr = which ? g_ptr_dn : g_ptr_up;
    int* cur = which ? g_cnt_dn : g_cnt_up;
    int tid = threadIdx.x;
    int g = (blockIdx.x * 256) / SCAN_BS;
    int contrib = (tid < g) ? g_bsum[which][tid] : 0;   // g <= 195 < 256
    s[tid] = contrib;
    __syncthreads();
    for (int off = 128; off; off >>= 1) {
        if (tid < off) s[tid] += s[tid + off];
        __syncthreads();
    }
    int prefix = s[0];
    int i = blockIdx.x * 256 + tid;
    if (i < NN) {
        int p = ptr[i] + prefix;
        ptr[i] = p;
        cur[i] = p;
    }
    if (i == 0) ptr[NN] = NNZC;
}

// 2 edges per thread -> 4 independent atomic/scatter chains.
__global__ void fill_kernel(const int* __restrict__ ru, const float* __restrict__ vu,
                            const int* __restrict__ rd, const float* __restrict__ vd) {
    int e2 = blockIdx.x * blockDim.x + threadIdx.x;
    if (e2 >= NNZC / 2) return;
    int2 r0 = ((const int2*)ru)[e2];
    int2 c0 = ((const int2*)(ru + NNZC))[e2];
    float2 v0 = ((const float2*)vu)[e2];
    int2 r1 = ((const int2*)rd)[e2];
    int2 c1 = ((const int2*)(rd + NNZC))[e2];
    float2 v1 = ((const float2*)vd)[e2];
    int pa = atomicAdd(&g_cnt_up[r0.x], 1);
    int pb = atomicAdd(&g_cnt_up[r0.y], 1);
    int pc = atomicAdd(&g_cnt_dn[r1.x], 1);
    int pd = atomicAdd(&g_cnt_dn[r1.y], 1);
    g_eu[pa] = make_int2(c0.x, __float_as_int(v0.x));
    g_eu[pb] = make_int2(c0.y, __float_as_int(v0.y));
    g_ed[pc] = make_int2(c1.x, __float_as_int(v1.x));
    g_ed[pd] = make_int2(c1.y, __float_as_int(v1.y));
}

// ---------------- layers 1/2 GEMM (f32x2) + fused T = exp(|h| @ a2) ----------------
// Two heads of width 16 concatenated (FO=32), W layout [2][FI][16], a2 [2][16].
// SRCHALF=1: stage X from g_Xa16 (half2). Writes fp16 H and T into S2a/S2b.
template <int FI, int NT, int SRCHALF>
__global__ __launch_bounds__(256) void gemm12_kernel(const float* __restrict__ Xext,
                                                     const float* __restrict__ W,
                                                     const float* __restrict__ a2) {
    constexpr int FO = 32;
    constexpr int G = 256 / FO;                 // 8
    constexpr int TN = NT / G;
    __shared__ unsigned long long Wsd[(FI / 2) * FO];   // paired (w_k, w_{k+1}) per output j
    __shared__ __align__(16) float Xs[NT * FI];
    __shared__ float a2s[FO];

    int tid = threadIdx.x;
    for (int i = tid; i < (FI / 2) * FO; i += 256) {
        int k2 = i / FO, j = i % FO;
        float wlo, whi;
        if (j < 16) {
            wlo = W[(2 * k2) * 16 + j];
            whi = W[(2 * k2 + 1) * 16 + j];
        } else {
            wlo = W[FI * 16 + (2 * k2) * 16 + (j - 16)];
            whi = W[FI * 16 + (2 * k2 + 1) * 16 + (j - 16)];
        }
        unsigned long long dd; PACK2(dd, wlo, whi);
        Wsd[i] = dd;
    }
    if (tid < FO) a2s[tid] = a2[tid];
    int nb = blockIdx.x * NT;
    if (SRCHALF) {
        const __half2* src = (const __half2*)g_Xa16 + (size_t)nb * (FI / 2);
        float2* dst = (float2*)Xs;
        for (int i = tid; i < NT * FI / 2; i += 256) dst[i] = __half22float2(src[i]);
    } else {
        const float4* src = (const float4*)(Xext + (size_t)nb * FI);
        float4* dst = (float4*)Xs;
        for (int i = tid; i < NT * FI / 4; i += 256) dst[i] = src[i];
    }
    __syncthreads();

    int j = tid % FO, grp = tid / FO, lane = tid & 31;
    unsigned long long acc[TN];
#pragma unroll
    for (int t = 0; t < TN; ++t) acc[t] = 0ull;
    const float4* Xs4 = (const float4*)Xs;
#pragma unroll 4
    for (int k4 = 0; k4 < FI / 4; ++k4) {
        unsigned long long w01 = Wsd[(2 * k4 + 0) * FO + j];
        unsigned long long w23 = Wsd[(2 * k4 + 1) * FO + j];
#pragma unroll
        for (int t = 0; t < TN; ++t) {
            float4 x = Xs4[(grp + G * t) * (FI / 4) + k4];
            unsigned long long x01, x23;
            PACK2(x01, x.x, x.y);
            PACK2(x23, x.z, x.w);
            FFMA2(acc[t], x01, w01);
            FFMA2(acc[t], x23, w23);
        }
    }
    float h[TN];
#pragma unroll
    for (int t = 0; t < TN; ++t) {
        h[t] = hsum2(acc[t]);
        int node = nb + grp + G * t;
        g_H16[(size_t)node * 32 + j] = __float2half_rn(h[t]);
    }
    float a = a2s[j];
#pragma unroll
    for (int t = 0; t < TN; ++t) {
        float v = fabsf(h[t]) * a;
        v += __shfl_xor_sync(0xffffffffu, v, 8);
        v += __shfl_xor_sync(0xffffffffu, v, 4);
        v += __shfl_xor_sync(0xffffffffu, v, 2);
        v += __shfl_xor_sync(0xffffffffu, v, 1);
        int node = nb + grp + G * t;
        if (lane == 0)  g_S2a[node] = __expf(v);   // head 0 (j 0..15)
        if (lane == 16) g_S2b[node] = __expf(v);   // head 1 (j 16..31)
    }
}

// ---------------- fused up+down agg, layers 1/2 (16 features/head, half2 loads) ----------------
// R9-style simple single-chain loops (ptxas batches the independent loads itself).
__global__ __launch_bounds__(256) void agg16c_kernel(int sel) {
    int gw = (blockIdx.x * blockDim.x + threadIdx.x) >> 5;
    int lane = threadIdx.x & 31;
    int sub = lane >> 3, f2 = lane & 7;
    const __half2* __restrict__ H2 = (const __half2*)g_H16;  // row = 16 half2

    float2 r0, r1;
    {   // head 0: up graph, half2 cols [0,8)
        int start = g_ptr_up[gw], end = g_ptr_up[gw + 1];
        float d = 0.f;
        float2 acc = make_float2(0.f, 0.f);
        for (int e = start + sub; e < end; e += 4) {
            int2 cv = g_eu[e];
            float t = g_S2a[cv.x];
            float w = t * __int_as_float(cv.y);
            d += t;
            float2 hv = __half22float2(H2[(size_t)cv.x * 16 + f2]);
            acc.x += w * hv.x;
            acc.y += w * hv.y;
        }
        acc.x += __shfl_xor_sync(0xffffffffu, acc.x, 8);
        acc.y += __shfl_xor_sync(0xffffffffu, acc.y, 8);
        d     += __shfl_xor_sync(0xffffffffu, d, 8);
        acc.x += __shfl_xor_sync(0xffffffffu, acc.x, 16);
        acc.y += __shfl_xor_sync(0xffffffffu, acc.y, 16);
        d     += __shfl_xor_sync(0xffffffffu, d, 16);
        float rd = (d > 0.f) ? 1.f / d : 0.f;
        r0 = make_float2(fmaxf(acc.x * rd, 0.f), fmaxf(acc.y * rd, 0.f));
    }
    {   // head 1: down graph, half2 cols [8,16)
        int start = g_ptr_dn[gw], end = g_ptr_dn[gw + 1];
        float d = 0.f;
        float2 acc = make_float2(0.f, 0.f);
        for (int e = start + sub; e < end; e += 4) {
            int2 cv = g_ed[e];
            float t = g_S2b[cv.x];
            float w = t * __int_as_float(cv.y);
            d += t;
            float2 hv = __half22float2(H2[(size_t)cv.x * 16 + 8 + f2]);
            acc.x += w * hv.x;
            acc.y += w * hv.y;
        }
        acc.x += __shfl_xor_sync(0xffffffffu, acc.x, 8);
        acc.y += __shfl_xor_sync(0xffffffffu, acc.y, 8);
        d     += __shfl_xor_sync(0xffffffffu, d, 8);
        acc.x += __shfl_xor_sync(0xffffffffu, acc.x, 16);
        acc.y += __shfl_xor_sync(0xffffffffu, acc.y, 16);
        d     += __shfl_xor_sync(0xffffffffu, d, 16);
        float rd = (d > 0.f) ? 1.f / d : 0.f;
        r1 = make_float2(fmaxf(acc.x * rd, 0.f), fmaxf(acc.y * rd, 0.f));
    }
    if (lane < 8) {
        __half2* X2 = sel ? (__half2*)g_Xb16 : (__half2*)g_Xa16;
        X2[gw * 16 + f2]     = __float22half2_rn(r0);
        X2[gw * 16 + 8 + f2] = __float22half2_rn(r1);
    }
}

// ---------------- layer-4 T kernel (f32x2): both heads in one launch ----------------
__global__ __launch_bounds__(256) void t4_kernel(const float* __restrict__ W4,
                                                 const float* __restrict__ a24) {
    constexpr int FI = 32, FO = 64;
    constexpr int NT = 64;
    constexpr int G = 256 / FO;   // 4
    constexpr int TN = NT / G;    // 16
    __shared__ unsigned long long Wsd[(FI / 2) * FO];
    __shared__ __align__(16) float Xs[NT * FI];
    __shared__ float a2s[FO];
    __shared__ float sred[8 * TN];

    int headsel = blockIdx.y;
    const float* W = W4 + headsel * FI * FO;
    const float* a2 = a24 + headsel * FO;

    int tid = threadIdx.x;
    for (int i = tid; i < (FI / 2) * FO; i += 256) {
        int k2 = i / FO, j = i % FO;
        unsigned long long dd;
        PACK2(dd, W[(2 * k2) * FO + j], W[(2 * k2 + 1) * FO + j]);
        Wsd[i] = dd;
    }
    if (tid < FO) a2s[tid] = a2[tid];
    int nb = blockIdx.x * NT;
    {
        const __half2* src = (const __half2*)g_Xb16 + (size_t)nb * 16;
        float2* dst = (float2*)Xs;
        for (int i = tid; i < NT * 16; i += 256) dst[i] = __half22float2(src[i]);
    }
    __syncthreads();

    int j = tid % FO, grp = tid / FO, lane = tid & 31;
    unsigned long long acc[TN];
#pragma unroll
    for (int t = 0; t < TN; ++t) acc[t] = 0ull;
    const float4* Xs4 = (const float4*)Xs;
#pragma unroll
    for (int k4 = 0; k4 < FI / 4; ++k4) {
        unsigned long long w01 = Wsd[(2 * k4 + 0) * FO + j];
        unsigned long long w23 = Wsd[(2 * k4 + 1) * FO + j];
#pragma unroll
        for (int t = 0; t < TN; ++t) {
            float4 x = Xs4[(grp + G * t) * (FI / 4) + k4];
            unsigned long long x01, x23;
            PACK2(x01, x.x, x.y);
            PACK2(x23, x.z, x.w);
            FFMA2(acc[t], x01, w01);
            FFMA2(acc[t], x23, w23);
        }
    }
    float a = a2s[j];
    int wib = tid >> 5;
#pragma unroll
    for (int t = 0; t < TN; ++t) {
        float v = fabsf(hsum2(acc[t])) * a;
        for (int off = 16; off; off >>= 1) v += __shfl_xor_sync(0xffffffffu, v, off);
        if (lane == 0) sred[wib * TN + t] = v;
    }
    __syncthreads();
    if (j == 0) {
        float* Tout = headsel ? g_S2b : g_S2a;
#pragma unroll
        for (int t = 0; t < TN; ++t) {
            int node = nb + grp + G * t;
            Tout[node] = __expf(sred[(2 * grp) * TN + t] + sred[(2 * grp + 1) * TN + t]);
        }
    }
}

// ---------------- layer-4 aggregation of Xb16 (32 features, up|dn -> U16[64]) ----------------
// R9-style simple loops, 2 sub-groups of 16 lanes.
__global__ __launch_bounds__(256) void agg4_kernel() {
    int gw = (blockIdx.x * blockDim.x + threadIdx.x) >> 5;
    int lane = threadIdx.x & 31;
    int sub = lane >> 4, f2 = lane & 15;
    const __half2* __restrict__ X2 = (const __half2*)g_Xb16;  // row = 16 half2

    float2 up, dn;
    {   // up graph
        int start = g_ptr_up[gw], end = g_ptr_up[gw + 1];
        float d = 0.f;
        float2 acc = make_float2(0.f, 0.f);
        for (int e = start + sub; e < end; e += 2) {
            int2 cv = g_eu[e];
            float t = g_S2a[cv.x];
            float w = t * __int_as_float(cv.y);
            d += t;
            float2 hv = __half22float2(X2[(size_t)cv.x * 16 + f2]);
            acc.x += w * hv.x;
            acc.y += w * hv.y;
        }
        acc.x += __shfl_xor_sync(0xffffffffu, acc.x, 16);
        acc.y += __shfl_xor_sync(0xffffffffu, acc.y, 16);
        d     += __shfl_xor_sync(0xffffffffu, d, 16);
        float rd = (d > 0.f) ? 1.f / d : 0.f;
        up = make_float2(acc.x * rd, acc.y * rd);
    }
    {   // down graph
        int start = g_ptr_dn[gw], end = g_ptr_dn[gw + 1];
        float d = 0.f;
        float2 acc = make_float2(0.f, 0.f);
        for (int e = start + sub; e < end; e += 2) {
            int2 cv = g_ed[e];
            float t = g_S2b[cv.x];
            float w = t * __int_as_float(cv.y);
            d += t;
            float2 hv = __half22float2(X2[(size_t)cv.x * 16 + f2]);
            acc.x += w * hv.x;
            acc.y += w * hv.y;
        }
        acc.x += __shfl_xor_sync(0xffffffffu, acc.x, 16);
        acc.y += __shfl_xor_sync(0xffffffffu, acc.y, 16);
        d     += __shfl_xor_sync(0xffffffffu, d, 16);
        float rd = (d > 0.f) ? 1.f / d : 0.f;
        dn = make_float2(acc.x * rd, acc.y * rd);
    }
    if (lane < 16) {
        __half2* U2 = (__half2*)g_U16;     // row = 32 half2: [0,16) up, [16,32) dn
        U2[gw * 32 + f2]      = __float22half2_rn(up);
        U2[gw * 32 + 16 + f2] = __float22half2_rn(dn);
    }
}

// ---------------- final GEMM (f32x2): out = relu(U16 @ W4flat) fused mean-pool ----------------
__global__ __launch_bounds__(256) void gemmfinal_kernel(const float* __restrict__ W4,
                                                        const int* __restrict__ batch) {
    constexpr int FI = 64, FO = 64;
    constexpr int NT = 64;
    constexpr int G = 4, TN = 16;
    __shared__ unsigned long long Wsd[(FI / 2) * FO];   // W4 flat [2][32][64] == [64][64]
    __shared__ __align__(16) float Xs[NT * FI];
    __shared__ float sred2[4][64];

    int tid = threadIdx.x;
    for (int i = tid; i < (FI / 2) * FO; i += 256) {
        int k2 = i / FO, j = i % FO;
        unsigned long long dd;
        PACK2(dd, W4[(2 * k2) * FO + j], W4[(2 * k2 + 1) * FO + j]);
        Wsd[i] = dd;
    }
    int nb = blockIdx.x * NT;
    {
        const __half2* src = (const __half2*)g_U16 + (size_t)nb * 32;
        float2* dst = (float2*)Xs;
        for (int i = tid; i < NT * 32; i += 256) dst[i] = __half22float2(src[i]);
    }
    __syncthreads();

    int j = tid % FO, grp = tid / FO;
    unsigned long long acc[TN];
#pragma unroll
    for (int t = 0; t < TN; ++t) acc[t] = 0ull;
    const float4* Xs4 = (const float4*)Xs;
#pragma unroll 4
    for (int k4 = 0; k4 < FI / 4; ++k4) {
        unsigned long long w01 = Wsd[(2 * k4 + 0) * FO + j];
        unsigned long long w23 = Wsd[(2 * k4 + 1) * FO + j];
#pragma unroll
        for (int t = 0; t < TN; ++t) {
            float4 x = Xs4[(grp + G * t) * (FI / 4) + k4];
            unsigned long long x01, x23;
            PACK2(x01, x.x, x.y);
            PACK2(x23, x.z, x.w);
            FFMA2(acc[t], x01, w01);
            FFMA2(acc[t], x23, w23);
        }
    }

    // pooled accumulation (batch sorted -> uniform iff first == last)
    int b0 = batch[nb];
    int bL = batch[nb + NT - 1];
    if (b0 == bL) {
        float s = 0.f;
#pragma unroll
        for (int t = 0; t < TN; ++t) s += fmaxf(hsum2(acc[t]), 0.f);
        sred2[grp][j] = s;
        __syncthreads();
        if (tid < 64) {
            float tot = sred2[0][tid] + sred2[1][tid] + sred2[2][tid] + sred2[3][tid];
            atomicAdd(&g_psum[b0 * 64 + tid], tot);
        }
        if (tid == 0) atomicAdd(&g_pcnt[b0], (float)NT);
    } else {
#pragma unroll
        for (int t = 0; t < TN; ++t) {
            int node = nb + grp + G * t;
            int b = batch[node];
            atomicAdd(&g_psum[b * 64 + j], fmaxf(hsum2(acc[t]), 0.f));
            if (j == 0) atomicAdd(&g_pcnt[b], 1.f);
        }
    }
}

__global__ void pool_softmax_kernel(float* __restrict__ out) {
    int g = blockIdx.x, j = threadIdx.x;
    __shared__ float rm[2], rs[2];
    float c = g_pcnt[g];
    float mean = g_psum[g * 64 + j] / fmaxf(c, 1.0f);
    float m = mean;
    for (int off = 16; off; off >>= 1) m = fmaxf(m, __shfl_xor_sync(0xffffffffu, m, off));
    if ((j & 31) == 0) rm[j >> 5] = m;
    __syncthreads();
    m = fmaxf(rm[0], rm[1]);
    float e = expf(mean - m);
    float s = e;
    for (int off = 16; off; off >>= 1) s += __shfl_xor_sync(0xffffffffu, s, off);
    if ((j & 31) == 0) rs[j >> 5] = s;
    __syncthreads();
    s = rs[0] + rs[1];
    out[g * 64 + j] = e / s;
}

// ---------------- launch ----------------
extern "C" void kernel_launch(void* const* d_in, const int* in_sizes, int n_in,
                              void* d_out, int out_size) {
    const float* X1   = (const float*)d_in[0];
    const int*   idxu = (const int*)d_in[1];
    const float* valu = (const float*)d_in[2];
    const int*   idxd = (const int*)d_in[3];
    const float* vald = (const float*)d_in[4];
    const int*   batch = (const int*)d_in[5];
    const float* W1  = (const float*)d_in[6];
    const float* a21 = (const float*)d_in[8];
    const float* W2  = (const float*)d_in[9];
    const float* a22 = (const float*)d_in[11];
    const float* W4  = (const float*)d_in[12];
    const float* a24 = (const float*)d_in[14];
    float* out = (float*)d_out;

    const int NB = (NN + 255) / 256;     // 782

    zero_kernel<<<NB, 256>>>();
    count_kernel<<<NNZC / 4 / 256, 256>>>(idxu, idxd);
    scan1_kernel<<<dim3(NBLK_SCAN, 2), SCAN_BS>>>();
    scan3_kernel<<<dim3(NB, 2), 256>>>();
    fill_kernel<<<NNZC / 2 / 256, 256>>>(idxu, valu, idxd, vald);

    // layer 1
    gemm12_kernel<128, 32, 0><<<NN / 32, 256>>>(X1, W1, a21);
    agg16c_kernel<<<NN / 8, 256>>>(0);          // -> g_Xa16
    // layer 2
    gemm12_kernel<32, 64, 1><<<NN / 64, 256>>>(nullptr, W2, a22);
    agg16c_kernel<<<NN / 8, 256>>>(1);          // -> g_Xb16
    // layer 4: both heads' T in one launch, aggregate Xb16, then GEMM+ReLU+pool
    t4_kernel<<<dim3(NN / 64, 2), 256>>>(W4, a24);
    agg4_kernel<<<NN / 8, 256>>>();
    gemmfinal_kernel<<<NN / 64, 256>>>(W4, batch);

    pool_softmax_kernel<<<NG, 64>>>(out);
}